// round 15
// baseline (speedup 1.0000x reference)
#include <cuda_runtime.h>
#include <cstdint>

#define E 256
#define SLEN 64
#define TLEN 512
#define CLU 8
#define NTHR 256
#define BPC 4

typedef unsigned long long u64;

// WH:  [k=256][768]: rank r owns cols [96r,96r+96): cc=3j+g -> w_hh[g*256+32r+j][k]
// WX:  [k=512][1024]: c<96: 3j+g -> w_ih[g*256+32r+j][k]; else zero pad.
// WVT: [k=256][256]: WVT[k][e] = W_w[e][k]  (v-partial weights, coalesced by e)
__device__ float4 g_WH[256 * 192];
__device__ float4 g_WX[512 * 256];
__device__ float4 g_WVT[256 * 64];

__global__ void prep(const float* __restrict__ Ww, const float* __restrict__ wih,
                     const float* __restrict__ whh) {
    int idx = blockIdx.x * blockDim.x + threadIdx.x;
    float* WH = (float*)g_WH;
    float* WX = (float*)g_WX;
    float* WVT = (float*)g_WVT;
    if (idx < 196608) {
        int k = idx / 768, c = idx - k * 768;
        int r = c / 96, cc = c - 96 * r;
        int j = cc / 3, g = cc - 3 * j;
        WH[idx] = whh[(g * 256 + 32 * r + j) * 256 + k];
    }
    int i2 = idx - 196608;
    if (i2 >= 0 && i2 < 524288) {
        int k = i2 >> 10, cg = i2 & 1023, r = cg >> 7, c = cg & 127;
        if (c < 96) {
            int j = c / 3, g = c - 3 * j;
            WX[i2] = wih[(g * 256 + 32 * r + j) * 512 + k];
        } else WX[i2] = 0.f;
    }
    int i3 = idx - 720896;
    if (i3 >= 0 && i3 < 65536) {
        int k = i3 >> 8, e = i3 & 255;
        WVT[i3] = Ww[e * 256 + k];
    }
}

// ---------------- helpers ----------------------------------------------------
__device__ __forceinline__ u64 f2x2(float a, float b) {
    u64 r; asm("mov.b64 %0,{%1,%2};" : "=l"(r) : "f"(a), "f"(b)); return r;
}
__device__ __forceinline__ void unpk(u64 v, float& a, float& b) {
    asm("mov.b64 {%0,%1},%2;" : "=f"(a), "=f"(b) : "l"(v));
}
__device__ __forceinline__ u64 fma2(u64 a, u64 b, u64 c) {
    u64 d; asm("fma.rn.f32x2 %0,%1,%2,%3;" : "=l"(d) : "l"(a), "l"(b), "l"(c)); return d;
}
__device__ __forceinline__ u64 mul2(u64 a, u64 b) {
    u64 d; asm("mul.rn.f32x2 %0,%1,%2;" : "=l"(d) : "l"(a), "l"(b)); return d;
}
__device__ __forceinline__ u64 add2(u64 a, u64 b) {
    u64 d; asm("add.rn.f32x2 %0,%1,%2;" : "=l"(d) : "l"(a), "l"(b)); return d;
}
__device__ __forceinline__ uint32_t s2u(const void* p) {
    return (uint32_t)__cvta_generic_to_shared(p);
}
__device__ __forceinline__ void stc64(uint32_t a, uint32_t rk, u64 v) {
    uint32_t ra;
    asm volatile("mapa.shared::cluster.u32 %0,%1,%2;" : "=r"(ra) : "r"(a), "r"(rk));
    asm volatile("st.shared::cluster.u64 [%0],%1;" ::"r"(ra), "l"(v) : "memory");
}
__device__ __forceinline__ void stc32(uint32_t a, uint32_t rk, float v) {
    uint32_t ra;
    asm volatile("mapa.shared::cluster.u32 %0,%1,%2;" : "=r"(ra) : "r"(a), "r"(rk));
    asm volatile("st.shared::cluster.f32 [%0],%1;" ::"r"(ra), "f"(v) : "memory");
}
__device__ __forceinline__ void csync() {
    asm volatile("barrier.cluster.arrive.aligned;" ::: "memory");
    asm volatile("barrier.cluster.wait.aligned;" ::: "memory");
}

struct __align__(16) SM {
    u64 hdup[256 * BPC];     // (h,h) per [k][bb]
    u64 lndup[512 * BPC];    // (y,y) per [k][bb] — written locally
    float part[8 * 514];     // matvec partials / ctx scratch
    float ctxh[8][260];      // raw ctx halves from all 8 ranks
    float vparts[8][256];    // v partials from all 8 ranks (own batch)
    float hloc[4][32];       // own-rank h chunk, 4 batches
    float2 mSall[8];         // (m,S) from all 8 ranks
    float v_own[E];
    float gh_loc[BPC * 96];
    float gx_loc[BPC * 96];
    float lngS[512];
    float lnbS[512];
    float muS[4];
    float rsS[4];
    uint32_t msk[256];
    float2 mS[8];
    float wgtS[8];
    float redA[12];
    float redB[12];
};

// gh: 96-col slice (this rank) x 4 batches over K=256; warp = 32-k partition.
__device__ __forceinline__ void matsliceH(const u64* __restrict__ Wq,
                                          const u64* __restrict__ hq,
                                          float* part, int lane, int warp, int rank) {
    int ll = lane < 24 ? lane : 23;
    u64 acc[2][4];
#pragma unroll
    for (int p = 0; p < 2; p++)
#pragma unroll
        for (int b = 0; b < 4; b++) acc[p][b] = 0ull;
    const u64* wp = Wq + (size_t)(warp * 32) * 384 + rank * 48 + 2 * ll;
    const u64* hp = hq + (warp * 32) * 4;
#pragma unroll 4
    for (int k = 0; k < 32; k++) {
        u64 w0 = wp[0], w1 = wp[1];
        wp += 384;
        u64 h0 = hp[0], h1 = hp[1], h2 = hp[2], h3 = hp[3];
        hp += 4;
        acc[0][0] = fma2(w0, h0, acc[0][0]); acc[1][0] = fma2(w1, h0, acc[1][0]);
        acc[0][1] = fma2(w0, h1, acc[0][1]); acc[1][1] = fma2(w1, h1, acc[1][1]);
        acc[0][2] = fma2(w0, h2, acc[0][2]); acc[1][2] = fma2(w1, h2, acc[1][2]);
        acc[0][3] = fma2(w0, h3, acc[0][3]); acc[1][3] = fma2(w1, h3, acc[1][3]);
    }
    if (lane < 24) {
#pragma unroll
        for (int p = 0; p < 2; p++)
#pragma unroll
            for (int b = 0; b < 4; b++)
                *(u64*)(part + warp * 388 + b * 96 + 4 * ll + 2 * p) = acc[p][b];
    }
}

// gx: 128-col slice (96 used) x 4 batches; warp = k-partition of NT*4.
template <int NT>
__device__ __forceinline__ void matslice2(const ulonglong2* __restrict__ Wq,
                                          const ulonglong2* __restrict__ hq,
                                          float* part, int lane, int warp, int rank) {
    u64 acc[2][4];
#pragma unroll
    for (int p = 0; p < 2; p++)
#pragma unroll
        for (int b = 0; b < 4; b++) acc[p][b] = 0ull;
    const ulonglong2* wp = Wq + (size_t)(warp * NT * 4) * 256 + rank * 32 + lane;
    const ulonglong2* hp = hq + (warp * NT * 4) * 2;
#pragma unroll 2
    for (int t = 0; t < NT; t++) {
        ulonglong2 w0 = wp[0], w1 = wp[256], w2 = wp[512], w3 = wp[768];
        wp += 1024;
        ulonglong2 h0a = hp[0], h0b = hp[1], h1a = hp[2], h1b = hp[3];
        ulonglong2 h2a = hp[4], h2b = hp[5], h3a = hp[6], h3b = hp[7];
        hp += 8;
        acc[0][0] = fma2(w0.x, h0a.x, acc[0][0]); acc[1][0] = fma2(w0.y, h0a.x, acc[1][0]);
        acc[0][1] = fma2(w0.x, h0a.y, acc[0][1]); acc[1][1] = fma2(w0.y, h0a.y, acc[1][1]);
        acc[0][2] = fma2(w0.x, h0b.x, acc[0][2]); acc[1][2] = fma2(w0.y, h0b.x, acc[1][2]);
        acc[0][3] = fma2(w0.x, h0b.y, acc[0][3]); acc[1][3] = fma2(w0.y, h0b.y, acc[1][3]);
        acc[0][0] = fma2(w1.x, h1a.x, acc[0][0]); acc[1][0] = fma2(w1.y, h1a.x, acc[1][0]);
        acc[0][1] = fma2(w1.x, h1a.y, acc[0][1]); acc[1][1] = fma2(w1.y, h1a.y, acc[1][1]);
        acc[0][2] = fma2(w1.x, h1b.x, acc[0][2]); acc[1][2] = fma2(w1.y, h1b.x, acc[1][2]);
        acc[0][3] = fma2(w1.x, h1b.y, acc[0][3]); acc[1][3] = fma2(w1.y, h1b.y, acc[1][3]);
        acc[0][0] = fma2(w2.x, h2a.x, acc[0][0]); acc[1][0] = fma2(w2.y, h2a.x, acc[1][0]);
        acc[0][1] = fma2(w2.x, h2a.y, acc[0][1]); acc[1][1] = fma2(w2.y, h2a.y, acc[1][1]);
        acc[0][2] = fma2(w2.x, h2b.x, acc[0][2]); acc[1][2] = fma2(w2.y, h2b.x, acc[1][2]);
        acc[0][3] = fma2(w2.x, h2b.y, acc[0][3]); acc[1][3] = fma2(w2.y, h2b.y, acc[1][3]);
        acc[0][0] = fma2(w3.x, h3a.x, acc[0][0]); acc[1][0] = fma2(w3.y, h3a.x, acc[1][0]);
        acc[0][1] = fma2(w3.x, h3a.y, acc[0][1]); acc[1][1] = fma2(w3.y, h3a.y, acc[1][1]);
        acc[0][2] = fma2(w3.x, h3b.x, acc[0][2]); acc[1][2] = fma2(w3.y, h3b.x, acc[1][2]);
        acc[0][3] = fma2(w3.x, h3b.y, acc[0][3]); acc[1][3] = fma2(w3.y, h3b.y, acc[1][3]);
    }
#pragma unroll
    for (int p = 0; p < 2; p++)
#pragma unroll
        for (int b = 0; b < 4; b++) {
            int x = b * 128 + 4 * lane + 2 * p;
            *(u64*)(part + warp * 514 + x) = acc[p][b];
        }
}

// v-partials from own h-chunk, scattered to batch-owner pairs.
__device__ __forceinline__ void vpart_scatter(SM* sm, int tid, uint32_t rank) {
    float a0 = 0.f, a1 = 0.f, a2 = 0.f, a3 = 0.f;
    const float* wv = (const float*)g_WVT + (size_t)(32 * rank) * 256 + tid;
#pragma unroll 8
    for (int j = 0; j < 32; j++) {
        float w = wv[(size_t)j * 256];
        a0 += w * sm->hloc[0][j];
        a1 += w * sm->hloc[1][j];
        a2 += w * sm->hloc[2][j];
        a3 += w * sm->hloc[3][j];
    }
    uint32_t av = s2u(&sm->vparts[rank][tid]);
    stc32(av, 0u, a0); stc32(av, 1u, a0);
    stc32(av, 2u, a1); stc32(av, 3u, a1);
    stc32(av, 4u, a2); stc32(av, 5u, a2);
    stc32(av, 6u, a3); stc32(av, 7u, a3);
}

__global__ void __cluster_dims__(CLU, 1, 1) __launch_bounds__(NTHR, 2)
gru(const float* __restrict__ sig, const float* __restrict__ bases,
    const uint32_t* __restrict__ mask, const float* __restrict__ Wb,
    const float* __restrict__ lng, const float* __restrict__ lnb,
    const float* __restrict__ bih, const float* __restrict__ bhh,
    const float* __restrict__ h0, float* __restrict__ out) {
    extern __shared__ char smraw[];
    SM* sm = (SM*)smraw;
    const int tid = threadIdx.x, lane = tid & 31, warp = tid >> 5;
    uint32_t rank;
    asm("mov.u32 %0,%%cluster_ctarank;" : "=r"(rank));
    const int b_base = (blockIdx.x >> 3) * BPC;
    const int b = b_base + (int)(rank >> 1);
    const int toff = (rank & 1) * 256;
    const float NEGINF = __int_as_float(0xff800000);

    float bihr = 0.f, bihz = 0.f, bihn = 0.f;
    float bhhr = 0.f, bhhz = 0.f, bhhn = 0.f, hreg = 0.f;
    const int gj = tid & 31, gbb = tid >> 5;
    if (tid < 128) {
        int i = 32 * rank + gj;
        bihr = bih[i]; bihz = bih[256 + i]; bihn = bih[512 + i];
        bhhr = bhh[i]; bhhz = bhh[256 + i]; bhhn = bhh[512 + i];
        hreg = h0[i];
        if (tid < 32) {
            float hv = h0[32 * rank + gj];
#pragma unroll
            for (int bb = 0; bb < BPC; bb++) sm->hloc[bb][gj] = hv;
        }
    }
    {
        float hv = h0[tid];
#pragma unroll
        for (int bb = 0; bb < BPC; bb++) sm->hdup[tid * BPC + bb] = f2x2(hv, hv);
        sm->lngS[tid] = lng[tid];       sm->lngS[256 + tid] = lng[256 + tid];
        sm->lnbS[tid] = lnb[tid];       sm->lnbS[256 + tid] = lnb[256 + tid];
    }
    const ulonglong2 wbA = ((const ulonglong2*)Wb)[2 * lane];
    const ulonglong2 wbB = ((const ulonglong2*)Wb)[2 * lane + 1];
    sm->msk[tid] = mask[(size_t)b * TLEN + toff + tid];
    __syncthreads();
    vpart_scatter(sm, tid, rank);   // initial v partials from h0
    csync();                        // publish hdup + vparts

    const ulonglong2* sq = (const ulonglong2*)(sig + (size_t)b * TLEN * E);

    for (int s = 0; s < SLEN; s++) {
        // ===== 1. assemble v for own batch from 8 rank partials ==============
        {
            float v = 0.f;
#pragma unroll
            for (int r = 0; r < 8; r++) v += sm->vparts[r][tid];
            sm->v_own[tid] = v;
        }
        __syncthreads();

        // ===== 2. Attention: own batch, own 256-row T-half, 32 rows/warp ====
        ulonglong2 vr0 = ((const ulonglong2*)sm->v_own)[2 * lane];
        ulonglong2 vr1 = ((const ulonglong2*)sm->v_own)[2 * lane + 1];
        ulonglong2 va, vb;
        va.x = add2(vr0.x, wbA.x); va.y = add2(vr0.y, wbA.y);
        vb.x = add2(vr1.x, wbB.x); vb.y = add2(vr1.y, wbB.y);
        float mrun = -1e30f, Ss = 0.f;
        u64 c0 = 0, c1 = 0, c2 = 0, c3 = 0;
#pragma unroll 2
        for (int g = 0; g < 8; g++) {
            int tl = warp * 32 + g * 4;
            size_t tg = (size_t)(toff + tl) * 64;
            ulonglong2 r0a = sq[tg + 2 * lane],       r0b = sq[tg + 2 * lane + 1];
            ulonglong2 r1a = sq[tg + 64 + 2 * lane],  r1b = sq[tg + 64 + 2 * lane + 1];
            ulonglong2 r2a = sq[tg + 128 + 2 * lane], r2b = sq[tg + 128 + 2 * lane + 1];
            ulonglong2 r3a = sq[tg + 192 + 2 * lane], r3b = sq[tg + 192 + 2 * lane + 1];
            auto dotp = [&](ulonglong2 ra, ulonglong2 rb) {
                u64 a = mul2(ra.x, va.x);
                a = fma2(ra.y, va.y, a);
                a = fma2(rb.x, vb.x, a);
                a = fma2(rb.y, vb.y, a);
                float lo, hi; unpk(a, lo, hi);
                return lo + hi;
            };
            float a0 = dotp(r0a, r0b), a1 = dotp(r1a, r1b);
            float a2 = dotp(r2a, r2b), a3 = dotp(r3a, r3b);
#pragma unroll
            for (int o = 16; o; o >>= 1) {
                a0 += __shfl_xor_sync(0xffffffffu, a0, o);
                a1 += __shfl_xor_sync(0xffffffffu, a1, o);
                a2 += __shfl_xor_sync(0xffffffffu, a2, o);
                a3 += __shfl_xor_sync(0xffffffffu, a3, o);
            }
            if (sm->msk[tl + 0]) a0 = NEGINF;
            if (sm->msk[tl + 1]) a1 = NEGINF;
            if (sm->msk[tl + 2]) a2 = NEGINF;
            if (sm->msk[tl + 3]) a3 = NEGINF;
            float mg = fmaxf(fmaxf(a0, a1), fmaxf(a2, a3));
            if (mg > mrun) {
                float sc = __expf(mrun - mg);
                mrun = mg; Ss *= sc;
                u64 sc2 = f2x2(sc, sc);
                c0 = mul2(c0, sc2); c1 = mul2(c1, sc2);
                c2 = mul2(c2, sc2); c3 = mul2(c3, sc2);
            }
            float p0 = __expf(a0 - mrun), p1 = __expf(a1 - mrun);
            float p2 = __expf(a2 - mrun), p3 = __expf(a3 - mrun);
            Ss += (p0 + p1) + (p2 + p3);
            u64 q0 = f2x2(p0, p0), q1 = f2x2(p1, p1), q2 = f2x2(p2, p2), q3 = f2x2(p3, p3);
            c0 = fma2(q0, r0a.x, c0); c1 = fma2(q0, r0a.y, c1);
            c2 = fma2(q0, r0b.x, c2); c3 = fma2(q0, r0b.y, c3);
            c0 = fma2(q1, r1a.x, c0); c1 = fma2(q1, r1a.y, c1);
            c2 = fma2(q1, r1b.x, c2); c3 = fma2(q1, r1b.y, c3);
            c0 = fma2(q2, r2a.x, c0); c1 = fma2(q2, r2a.y, c1);
            c2 = fma2(q2, r2b.x, c2); c3 = fma2(q2, r2b.y, c3);
            c0 = fma2(q3, r3a.x, c0); c1 = fma2(q3, r3a.y, c1);
            c2 = fma2(q3, r3b.x, c2); c3 = fma2(q3, r3b.y, c3);
        }
        {
            u64* cw = (u64*)sm->part + warp * 132 + lane * 4;
            cw[0] = c0; cw[1] = c1; cw[2] = c2; cw[3] = c3;
            if (lane == 0) sm->mS[warp] = make_float2(mrun, Ss);
        }
        __syncthreads();
        if (tid < 32) {
            float mw = (lane < 8) ? sm->mS[lane].x : NEGINF;
            float Sw = (lane < 8) ? sm->mS[lane].y : 0.f;
            float m = mw;
#pragma unroll
            for (int o = 16; o; o >>= 1) m = fmaxf(m, __shfl_xor_sync(0xffffffffu, m, o));
            float wgt = __expf(mw - m);
            float Sc = Sw * wgt;
#pragma unroll
            for (int o = 16; o; o >>= 1) Sc += __shfl_xor_sync(0xffffffffu, Sc, o);
            if (lane < 8) sm->wgtS[lane] = wgt;
            if (lane == 0) {
                u64 msv = f2x2(m, Sc);
                uint32_t am = s2u(&sm->mSall[rank]);
#pragma unroll
                for (uint32_t rr = 0; rr < CLU; rr++) stc64(am, rr, msv);
            }
        }
        __syncthreads();
        {   // combine warp ctx partials; broadcast raw half to all 8 ranks
            float acc = 0.f;
#pragma unroll
            for (int w = 0; w < 8; w++) acc += sm->part[w * 264 + tid] * sm->wgtS[w];
            uint32_t ad = s2u(&sm->ctxh[rank][tid]);
#pragma unroll
            for (uint32_t rr = 0; rr < CLU; rr++) stc32(ad, rr, acc);
        }
        __syncthreads();  // ctx partial reads done; part free for gh matvec

        // ===== 3. gh matvec (reads hdup; before csync#A so reads precede
        //          any remote hdup writes, which occur only post-csync#A) ====
        matsliceH((const u64*)g_WH, (const u64*)sm->hdup, sm->part, lane, warp, rank);
        __syncthreads();
        if (tid < 192) {
            int bb = tid / 48, cu = tid - 48 * bb;
            u64 s2 = 0ull;
#pragma unroll
            for (int w = 0; w < 8; w++)
                s2 = add2(s2, *(const u64*)(sm->part + w * 388 + bb * 96 + 2 * cu));
            *(u64*)(&sm->gh_loc[bb * 96 + 2 * cu]) = s2;
        }
        csync();  // #A: ctxh + mSall published everywhere

        // ===== 4. Redundant merge + LN for all 4 batches (local) ============
        {
            int bb = tid >> 6, e4 = (tid & 63) * 4;
            float2 m0 = sm->mSall[2 * bb], m1 = sm->mSall[2 * bb + 1];
            float m = fmaxf(m0.x, m1.x);
            float w0 = __expf(m0.x - m), w1 = __expf(m1.x - m);
            float invS = 1.f / (m0.y * w0 + m1.y * w1);
            float4 cA = *(float4*)&sm->ctxh[2 * bb][e4];
            float4 cB = *(float4*)&sm->ctxh[2 * bb + 1][e4];
            float4 cm;
            cm.x = (cA.x * w0 + cB.x * w1) * invS;
            cm.y = (cA.y * w0 + cB.y * w1) * invS;
            cm.z = (cA.z * w0 + cB.z * w1) * invS;
            cm.w = (cA.w * w0 + cB.w * w1) * invS;
            *(float4*)&sm->ctxh[2 * bb][e4] = cm;
        }
        __syncthreads();
        {
            int bb = warp >> 1, half = warp & 1;
            float s1, s2;
            if (half == 0) {
                const float4* xb = (const float4*)(bases +
                    ((size_t)(b_base + bb) * SLEN + s) * E);
                float4 xa = xb[2 * lane], xc = xb[2 * lane + 1];
                s1 = (xa.x + xa.y + xa.z + xa.w) + (xc.x + xc.y + xc.z + xc.w);
                s2 = xa.x * xa.x + xa.y * xa.y + xa.z * xa.z + xa.w * xa.w +
                     xc.x * xc.x + xc.y * xc.y + xc.z * xc.z + xc.w * xc.w;
            } else {
                const float4* cb = (const float4*)&sm->ctxh[2 * bb][0];
                float4 xa = cb[2 * lane], xc = cb[2 * lane + 1];
                s1 = (xa.x + xa.y + xa.z + xa.w) + (xc.x + xc.y + xc.z + xc.w);
                s2 = xa.x * xa.x + xa.y * xa.y + xa.z * xa.z + xa.w * xa.w +
                     xc.x * xc.x + xc.y * xc.y + xc.z * xc.z + xc.w * xc.w;
            }
#pragma unroll
            for (int o = 16; o; o >>= 1) {
                s1 += __shfl_xor_sync(0xffffffffu, s1, o);
                s2 += __shfl_xor_sync(0xffffffffu, s2, o);
            }
            if (lane == 0) { sm->redA[warp] = s1; sm->redB[warp] = s2; }
            __syncthreads();
            if (tid < 4) {
                float t1 = sm->redA[2 * tid] + sm->redA[2 * tid + 1];
                float t2 = sm->redB[2 * tid] + sm->redB[2 * tid + 1];
                float mu = t1 * (1.f / 512.f);
                float var = t2 * (1.f / 512.f) - mu * mu;
                sm->muS[tid] = mu;
                sm->rsS[tid] = rsqrtf(var + 1e-5f);
            }
            __syncthreads();
        }
        {
            float g0 = sm->lngS[tid], b0v = sm->lnbS[tid];
            float g1 = sm->lngS[256 + tid], b1v = sm->lnbS[256 + tid];
#pragma unroll
            for (int bb = 0; bb < BPC; bb++) {
                float mu = sm->muS[bb], rs = sm->rsS[bb];
                float xv = bases[((size_t)(b_base + bb) * SLEN + s) * E + tid];
                float cv = sm->ctxh[2 * bb][tid];
                float y0 = (xv - mu) * rs * g0 + b0v;
                float y1 = (cv - mu) * rs * g1 + b1v;
                sm->lndup[(size_t)tid * BPC + bb] = f2x2(y0, y0);
                sm->lndup[(size_t)(256 + tid) * BPC + bb] = f2x2(y1, y1);
            }
        }
        __syncthreads();

        // ===== 5. Phase C: gx (local triplets), 4 batches ====================
        matslice2<16>((const ulonglong2*)g_WX, (const ulonglong2*)sm->lndup,
                      sm->part, lane, warp, rank);
        __syncthreads();
        {
            int x = 2 * tid;
            u64 s2 = 0ull;
#pragma unroll
            for (int w = 0; w < 8; w++) s2 = add2(s2, *(const u64*)(sm->part + w * 514 + x));
            int bb = x >> 7, c = x & 127;
            if (c < 96) *(u64*)(&sm->gx_loc[bb * 96 + c]) = s2;
        }
        __syncthreads();

        // ===== 6. Gates; broadcast h; compute + scatter v-partials ==========
        if (tid < 128) {
            int base = gbb * 96 + 3 * gj;
            float gxr = sm->gx_loc[base], gxz = sm->gx_loc[base + 1], gxn = sm->gx_loc[base + 2];
            float ghr = sm->gh_loc[base], ghz = sm->gh_loc[base + 1], ghn = sm->gh_loc[base + 2];
            float r = 1.f / (1.f + __expf(-(gxr + bihr + ghr + bhhr)));
            float z = 1.f / (1.f + __expf(-(gxz + bihz + ghz + bhhz)));
            float n = tanhf(gxn + bihn + r * (ghn + bhhn));
            hreg = (1.f - z) * n + z * hreg;
            int i = 32 * rank + gj;
            out[(((size_t)(b_base + gbb)) * SLEN + s) * E + i] = hreg;
            sm->hloc[gbb][gj] = hreg;
            u64 h2 = f2x2(hreg, hreg);
            uint32_t ah = s2u(&sm->hdup[i * BPC + gbb]);
#pragma unroll
            for (uint32_t rr = 0; rr < CLU; rr++) stc64(ah, rr, h2);
        }
        __syncthreads();  // hloc visible to all threads
        vpart_scatter(sm, tid, rank);
        csync();  // #B: hdup + vparts for step s+1 published
    }
}

extern "C" void kernel_launch(void* const* d_in, const int* in_sizes, int n_in,
                              void* d_out, int out_size) {
    const float* sig = (const float*)d_in[0];
    const float* bases = (const float*)d_in[1];
    const uint32_t* mask = (const uint32_t*)d_in[2];
    const float* Ww = (const float*)d_in[3];
    const float* Wb = (const float*)d_in[4];
    const float* lng = (const float*)d_in[5];
    const float* lnb = (const float*)d_in[6];
    const float* wih = (const float*)d_in[7];
    const float* bihp = (const float*)d_in[8];
    const float* whh = (const float*)d_in[9];
    const float* bhhp = (const float*)d_in[10];
    const float* h0 = (const float*)d_in[11];
    float* out = (float*)d_out;

    cudaFuncSetAttribute(gru, cudaFuncAttributeMaxDynamicSharedMemorySize,
                         (int)sizeof(SM));
    prep<<<3072, 256>>>(Ww, wih, whh);
    gru<<<256, NTHR, sizeof(SM)>>>(sig, bases, mask, Wb, lng, lnb, bihp, bhhp, h0, out);
}

// round 16
// speedup vs baseline: 1.1115x; 1.1115x over previous
#include <cuda_runtime.h>
#include <cstdint>

#define E 256
#define SLEN 64
#define TLEN 512
#define CLU 8
#define NTHR 256
#define BPC 4

typedef unsigned long long u64;

// WA: [k=256][1024 cols]. Rank r owns cols [128r,128r+128):
//   c<32: W_w row (32r+c) (v, scattered to batch-owner pair)
//   c>=32: cc=c-32=3j+g: w_hh row (g*256+32r+j) (gh triplets, local)
// WX: [k=512][1024]: c<96: 3j+g -> w_ih row (g*256+32r+j); else zero pad.
__device__ float4 g_WA[256 * 256];
__device__ float4 g_WX[512 * 256];

__global__ void prep(const float* __restrict__ Ww, const float* __restrict__ wih,
                     const float* __restrict__ whh) {
    int idx = blockIdx.x * blockDim.x + threadIdx.x;
    float* WA = (float*)g_WA;
    float* WX = (float*)g_WX;
    if (idx < 256 * 1024) {
        int k = idx >> 10, cg = idx & 1023, r = cg >> 7, c = cg & 127;
        if (c < 32) WA[idx] = Ww[(32 * r + c) * 256 + k];
        else {
            int cc = c - 32, j = cc / 3, g = cc - 3 * j;
            WA[idx] = whh[(g * 256 + 32 * r + j) * 256 + k];
        }
    }
    int idx2 = idx - 256 * 1024;
    if (idx2 >= 0 && idx2 < 512 * 1024) {
        int k = idx2 >> 10, cg = idx2 & 1023, r = cg >> 7, c = cg & 127;
        if (c < 96) {
            int j = c / 3, g = c - 3 * j;
            WX[idx2] = wih[(g * 256 + 32 * r + j) * 512 + k];
        } else WX[idx2] = 0.f;
    }
}

// ---------------- helpers ----------------------------------------------------
__device__ __forceinline__ u64 f2x2(float a, float b) {
    u64 r; asm("mov.b64 %0,{%1,%2};" : "=l"(r) : "f"(a), "f"(b)); return r;
}
__device__ __forceinline__ void unpk(u64 v, float& a, float& b) {
    asm("mov.b64 {%0,%1},%2;" : "=f"(a), "=f"(b) : "l"(v));
}
__device__ __forceinline__ u64 fma2(u64 a, u64 b, u64 c) {
    u64 d; asm("fma.rn.f32x2 %0,%1,%2,%3;" : "=l"(d) : "l"(a), "l"(b), "l"(c)); return d;
}
__device__ __forceinline__ u64 mul2(u64 a, u64 b) {
    u64 d; asm("mul.rn.f32x2 %0,%1,%2;" : "=l"(d) : "l"(a), "l"(b)); return d;
}
__device__ __forceinline__ u64 add2(u64 a, u64 b) {
    u64 d; asm("add.rn.f32x2 %0,%1,%2;" : "=l"(d) : "l"(a), "l"(b)); return d;
}
__device__ __forceinline__ uint32_t s2u(const void* p) {
    return (uint32_t)__cvta_generic_to_shared(p);
}
__device__ __forceinline__ void stc64(uint32_t a, uint32_t rk, u64 v) {
    uint32_t ra;
    asm volatile("mapa.shared::cluster.u32 %0,%1,%2;" : "=r"(ra) : "r"(a), "r"(rk));
    asm volatile("st.shared::cluster.u64 [%0],%1;" ::"r"(ra), "l"(v) : "memory");
}
__device__ __forceinline__ void stc32(uint32_t a, uint32_t rk, float v) {
    uint32_t ra;
    asm volatile("mapa.shared::cluster.u32 %0,%1,%2;" : "=r"(ra) : "r"(a), "r"(rk));
    asm volatile("st.shared::cluster.f32 [%0],%1;" ::"r"(ra), "f"(v) : "memory");
}
__device__ __forceinline__ void csync() {
    asm volatile("barrier.cluster.arrive.aligned;" ::: "memory");
    asm volatile("barrier.cluster.wait.aligned;" ::: "memory");
}
__device__ __forceinline__ float pick(u64 v, int comp) {
    float lo, hi; unpk(v, lo, hi);
    return comp ? hi : lo;
}

struct __align__(16) SM {
    u64 hpair[256 * 2];      // (h_{2p}, h_{2p+1}) per [k][p]
    u64 lnpair[512 * 2];     // (y_{2p}, y_{2p+1}) per [k][p] — local only
    float part[8 * 514];     // matvec partials / ctx scratch
    float ctxh[8][260];      // raw ctx halves from all 8 ranks
    float2 mSall[8];         // (m,S) from all 8 ranks
    float v_own[E];
    u64 ghpair[96][2];       // gh pairs [cc][p]
    u64 gxpair[96][2];       // gx pairs [cc][p]
    float hstage[4][33];     // gate outputs staging for pair-broadcast
    float lngS[512];
    float lnbS[512];
    float muS[4];
    float rsS[4];
    uint32_t msk[256];
    float2 mS[8];
    float wgtS[8];
    float redA[12];
    float redB[12];
};

// Batch-pair packed matvec: 4 cols/lane x 2 batch-pairs; warp = KW k's.
template <int KW>
__device__ __forceinline__ void matpair(const float4* __restrict__ W4,
                                        const u64* __restrict__ hp_,
                                        float* part, int lane, int warp, int rank) {
    u64 acc[4][2];
#pragma unroll
    for (int c = 0; c < 4; c++) { acc[c][0] = 0ull; acc[c][1] = 0ull; }
    const float4* wp = W4 + (size_t)(warp * KW) * 256 + rank * 32 + lane;
    const u64* hp = hp_ + (warp * KW) * 2;
#pragma unroll 4
    for (int k = 0; k < KW; k++) {
        float4 w = wp[0]; wp += 256;
        u64 h0 = hp[0], h1 = hp[1]; hp += 2;
        u64 w0 = f2x2(w.x, w.x), w1 = f2x2(w.y, w.y);
        u64 w2 = f2x2(w.z, w.z), w3 = f2x2(w.w, w.w);
        acc[0][0] = fma2(w0, h0, acc[0][0]); acc[0][1] = fma2(w0, h1, acc[0][1]);
        acc[1][0] = fma2(w1, h0, acc[1][0]); acc[1][1] = fma2(w1, h1, acc[1][1]);
        acc[2][0] = fma2(w2, h0, acc[2][0]); acc[2][1] = fma2(w2, h1, acc[2][1]);
        acc[3][0] = fma2(w3, h0, acc[3][0]); acc[3][1] = fma2(w3, h1, acc[3][1]);
    }
#pragma unroll
    for (int c = 0; c < 4; c++)
#pragma unroll
        for (int p = 0; p < 2; p++)
            *(u64*)(part + warp * 514 + 2 * (p * 128 + 4 * lane + c)) = acc[c][p];
}

__global__ void __cluster_dims__(CLU, 1, 1) __launch_bounds__(NTHR, 2)
gru(const float* __restrict__ sig, const float* __restrict__ bases,
    const uint32_t* __restrict__ mask, const float* __restrict__ Wb,
    const float* __restrict__ lng, const float* __restrict__ lnb,
    const float* __restrict__ bih, const float* __restrict__ bhh,
    const float* __restrict__ h0, float* __restrict__ out) {
    extern __shared__ char smraw[];
    SM* sm = (SM*)smraw;
    const int tid = threadIdx.x, lane = tid & 31, warp = tid >> 5;
    uint32_t rank;
    asm("mov.u32 %0,%%cluster_ctarank;" : "=r"(rank));
    const int b_base = (blockIdx.x >> 3) * BPC;
    const int b = b_base + (int)(rank >> 1);
    const int toff = (rank & 1) * 256;
    const float NEGINF = __int_as_float(0xff800000);

    float bihr = 0.f, bihz = 0.f, bihn = 0.f;
    float bhhr = 0.f, bhhz = 0.f, bhhn = 0.f, hreg = 0.f;
    const int gj = tid & 31, gbb = tid >> 5;
    if (tid < 128) {
        int i = 32 * rank + gj;
        bihr = bih[i]; bihz = bih[256 + i]; bihn = bih[512 + i];
        bhhr = bhh[i]; bhhz = bhh[256 + i]; bhhn = bhh[512 + i];
        hreg = h0[i];
    }
    {
        float hv = h0[tid];
        u64 h2 = f2x2(hv, hv);   // h0 identical across batches
        sm->hpair[tid * 2 + 0] = h2;
        sm->hpair[tid * 2 + 1] = h2;
        sm->lngS[tid] = lng[tid];       sm->lngS[256 + tid] = lng[256 + tid];
        sm->lnbS[tid] = lnb[tid];       sm->lnbS[256 + tid] = lnb[256 + tid];
    }
    const ulonglong2 wbA = ((const ulonglong2*)Wb)[2 * lane];
    const ulonglong2 wbB = ((const ulonglong2*)Wb)[2 * lane + 1];
    sm->msk[tid] = mask[(size_t)b * TLEN + toff + tid];
    __syncthreads();
    csync();

    const ulonglong2* sq = (const ulonglong2*)(sig + (size_t)b * TLEN * E);

    for (int s = 0; s < SLEN; s++) {
        // ===== Phase A: v (to batch-owner pair) + gh (local), packed ========
        matpair<32>(g_WA, sm->hpair, sm->part, lane, warp, rank);
        __syncthreads();
        {
            int x = tid;  // u64 slot: p = x>>7, col c = x&127
            u64 s2 = 0ull;
#pragma unroll
            for (int w = 0; w < 8; w++)
                s2 = add2(s2, *(const u64*)(sm->part + w * 514 + 2 * x));
            int p = x >> 7, c = x & 127;
            if (c < 32) {  // lo -> batch 2p (ranks 4p,4p+1), hi -> 2p+1
                float lo, hi; unpk(s2, lo, hi);
                uint32_t a = s2u(&sm->v_own[32 * rank + c]);
                stc32(a, (uint32_t)(4 * p + 0), lo);
                stc32(a, (uint32_t)(4 * p + 1), lo);
                stc32(a, (uint32_t)(4 * p + 2), hi);
                stc32(a, (uint32_t)(4 * p + 3), hi);
            } else sm->ghpair[c - 32][p] = s2;
        }
        csync();  // #1: v ready

        // ===== Attention: own batch, own 256-row T-half, 32 rows/warp =======
        ulonglong2 vr0 = ((const ulonglong2*)sm->v_own)[2 * lane];
        ulonglong2 vr1 = ((const ulonglong2*)sm->v_own)[2 * lane + 1];
        ulonglong2 va, vb;
        va.x = add2(vr0.x, wbA.x); va.y = add2(vr0.y, wbA.y);
        vb.x = add2(vr1.x, wbB.x); vb.y = add2(vr1.y, wbB.y);
        float mrun = -1e30f, Ss = 0.f;
        u64 c0 = 0, c1 = 0, c2 = 0, c3 = 0;
#pragma unroll 2
        for (int g = 0; g < 8; g++) {
            int tl = warp * 32 + g * 4;
            size_t tg = (size_t)(toff + tl) * 64;
            ulonglong2 r0a = sq[tg + 2 * lane],       r0b = sq[tg + 2 * lane + 1];
            ulonglong2 r1a = sq[tg + 64 + 2 * lane],  r1b = sq[tg + 64 + 2 * lane + 1];
            ulonglong2 r2a = sq[tg + 128 + 2 * lane], r2b = sq[tg + 128 + 2 * lane + 1];
            ulonglong2 r3a = sq[tg + 192 + 2 * lane], r3b = sq[tg + 192 + 2 * lane + 1];
            auto dotp = [&](ulonglong2 ra, ulonglong2 rb) {
                u64 a = mul2(ra.x, va.x);
                a = fma2(ra.y, va.y, a);
                a = fma2(rb.x, vb.x, a);
                a = fma2(rb.y, vb.y, a);
                float lo, hi; unpk(a, lo, hi);
                return lo + hi;
            };
            float a0 = dotp(r0a, r0b), a1 = dotp(r1a, r1b);
            float a2 = dotp(r2a, r2b), a3 = dotp(r3a, r3b);
#pragma unroll
            for (int o = 16; o; o >>= 1) {
                a0 += __shfl_xor_sync(0xffffffffu, a0, o);
                a1 += __shfl_xor_sync(0xffffffffu, a1, o);
                a2 += __shfl_xor_sync(0xffffffffu, a2, o);
                a3 += __shfl_xor_sync(0xffffffffu, a3, o);
            }
            if (sm->msk[tl + 0]) a0 = NEGINF;
            if (sm->msk[tl + 1]) a1 = NEGINF;
            if (sm->msk[tl + 2]) a2 = NEGINF;
            if (sm->msk[tl + 3]) a3 = NEGINF;
            float mg = fmaxf(fmaxf(a0, a1), fmaxf(a2, a3));
            if (mg > mrun) {
                float sc = __expf(mrun - mg);
                mrun = mg; Ss *= sc;
                u64 sc2 = f2x2(sc, sc);
                c0 = mul2(c0, sc2); c1 = mul2(c1, sc2);
                c2 = mul2(c2, sc2); c3 = mul2(c3, sc2);
            }
            float p0 = __expf(a0 - mrun), p1 = __expf(a1 - mrun);
            float p2 = __expf(a2 - mrun), p3 = __expf(a3 - mrun);
            Ss += (p0 + p1) + (p2 + p3);
            u64 q0 = f2x2(p0, p0), q1 = f2x2(p1, p1), q2 = f2x2(p2, p2), q3 = f2x2(p3, p3);
            c0 = fma2(q0, r0a.x, c0); c1 = fma2(q0, r0a.y, c1);
            c2 = fma2(q0, r0b.x, c2); c3 = fma2(q0, r0b.y, c3);
            c0 = fma2(q1, r1a.x, c0); c1 = fma2(q1, r1a.y, c1);
            c2 = fma2(q1, r1b.x, c2); c3 = fma2(q1, r1b.y, c3);
            c0 = fma2(q2, r2a.x, c0); c1 = fma2(q2, r2a.y, c1);
            c2 = fma2(q2, r2b.x, c2); c3 = fma2(q2, r2b.y, c3);
            c0 = fma2(q3, r3a.x, c0); c1 = fma2(q3, r3a.y, c1);
            c2 = fma2(q3, r3b.x, c2); c3 = fma2(q3, r3b.y, c3);
        }
        {
            u64* cw = (u64*)sm->part + warp * 132 + lane * 4;
            cw[0] = c0; cw[1] = c1; cw[2] = c2; cw[3] = c3;
            if (lane == 0) sm->mS[warp] = make_float2(mrun, Ss);
        }
        __syncthreads();
        if (tid < 32) {
            float mw = (lane < 8) ? sm->mS[lane].x : NEGINF;
            float Sw = (lane < 8) ? sm->mS[lane].y : 0.f;
            float m = mw;
#pragma unroll
            for (int o = 16; o; o >>= 1) m = fmaxf(m, __shfl_xor_sync(0xffffffffu, m, o));
            float wgt = __expf(mw - m);
            float Sc = Sw * wgt;
#pragma unroll
            for (int o = 16; o; o >>= 1) Sc += __shfl_xor_sync(0xffffffffu, Sc, o);
            if (lane < 8) sm->wgtS[lane] = wgt;
            if (lane == 0) {
                u64 msv = f2x2(m, Sc);
                uint32_t am = s2u(&sm->mSall[rank]);
#pragma unroll
                for (uint32_t rr = 0; rr < CLU; rr++) stc64(am, rr, msv);
            }
        }
        __syncthreads();
        {   // combine warp ctx partials; broadcast raw half to all 8 ranks
            float acc = 0.f;
#pragma unroll
            for (int w = 0; w < 8; w++) acc += sm->part[w * 264 + tid] * sm->wgtS[w];
            uint32_t ad = s2u(&sm->ctxh[rank][tid]);
#pragma unroll
            for (uint32_t rr = 0; rr < CLU; rr++) stc32(ad, rr, acc);
        }
        csync();  // #2: all ctx halves + (m,S) present everywhere

        // ===== Redundant merge + LN for all 4 batches (local) ===============
        {
            int bb = tid >> 6, e4 = (tid & 63) * 4;
            float2 m0 = sm->mSall[2 * bb], m1 = sm->mSall[2 * bb + 1];
            float m = fmaxf(m0.x, m1.x);
            float w0 = __expf(m0.x - m), w1 = __expf(m1.x - m);
            float invS = 1.f / (m0.y * w0 + m1.y * w1);
            float4 cA = *(float4*)&sm->ctxh[2 * bb][e4];
            float4 cB = *(float4*)&sm->ctxh[2 * bb + 1][e4];
            float4 cm;
            cm.x = (cA.x * w0 + cB.x * w1) * invS;
            cm.y = (cA.y * w0 + cB.y * w1) * invS;
            cm.z = (cA.z * w0 + cB.z * w1) * invS;
            cm.w = (cA.w * w0 + cB.w * w1) * invS;
            *(float4*)&sm->ctxh[2 * bb][e4] = cm;
        }
        __syncthreads();
        {
            int bb = warp >> 1, half = warp & 1;
            float s1, s2;
            if (half == 0) {
                const float4* xb = (const float4*)(bases +
                    ((size_t)(b_base + bb) * SLEN + s) * E);
                float4 xa = xb[2 * lane], xc = xb[2 * lane + 1];
                s1 = (xa.x + xa.y + xa.z + xa.w) + (xc.x + xc.y + xc.z + xc.w);
                s2 = xa.x * xa.x + xa.y * xa.y + xa.z * xa.z + xa.w * xa.w +
                     xc.x * xc.x + xc.y * xc.y + xc.z * xc.z + xc.w * xc.w;
            } else {
                const float4* cb = (const float4*)&sm->ctxh[2 * bb][0];
                float4 xa = cb[2 * lane], xc = cb[2 * lane + 1];
                s1 = (xa.x + xa.y + xa.z + xa.w) + (xc.x + xc.y + xc.z + xc.w);
                s2 = xa.x * xa.x + xa.y * xa.y + xa.z * xa.z + xa.w * xa.w +
                     xc.x * xc.x + xc.y * xc.y + xc.z * xc.z + xc.w * xc.w;
            }
#pragma unroll
            for (int o = 16; o; o >>= 1) {
                s1 += __shfl_xor_sync(0xffffffffu, s1, o);
                s2 += __shfl_xor_sync(0xffffffffu, s2, o);
            }
            if (lane == 0) { sm->redA[warp] = s1; sm->redB[warp] = s2; }
            __syncthreads();
            if (tid < 4) {
                float t1 = sm->redA[2 * tid] + sm->redA[2 * tid + 1];
                float t2 = sm->redB[2 * tid] + sm->redB[2 * tid + 1];
                float mu = t1 * (1.f / 512.f);
                float var = t2 * (1.f / 512.f) - mu * mu;
                sm->muS[tid] = mu;
                sm->rsS[tid] = rsqrtf(var + 1e-5f);
            }
            __syncthreads();
        }
        {   // y-write, batch-pair packed
            float g0 = sm->lngS[tid], b0v = sm->lnbS[tid];
            float g1 = sm->lngS[256 + tid], b1v = sm->lnbS[256 + tid];
#pragma unroll
            for (int p = 0; p < 2; p++) {
                float mu0 = sm->muS[2 * p], rs0 = sm->rsS[2 * p];
                float mu1 = sm->muS[2 * p + 1], rs1 = sm->rsS[2 * p + 1];
                float xv0 = bases[((size_t)(b_base + 2 * p) * SLEN + s) * E + tid];
                float xv1 = bases[((size_t)(b_base + 2 * p + 1) * SLEN + s) * E + tid];
                float cv0 = sm->ctxh[4 * p][tid];
                float cv1 = sm->ctxh[4 * p + 2][tid];
                sm->lnpair[tid * 2 + p] =
                    f2x2((xv0 - mu0) * rs0 * g0 + b0v, (xv1 - mu1) * rs1 * g0 + b0v);
                sm->lnpair[(256 + tid) * 2 + p] =
                    f2x2((cv0 - mu0) * rs0 * g1 + b1v, (cv1 - mu1) * rs1 * g1 + b1v);
            }
        }
        __syncthreads();

        // ===== Phase C: gx (local triplets), packed ==========================
        matpair<64>(g_WX, sm->lnpair, sm->part, lane, warp, rank);
        __syncthreads();
        {
            int x = tid;
            u64 s2 = 0ull;
#pragma unroll
            for (int w = 0; w < 8; w++)
                s2 = add2(s2, *(const u64*)(sm->part + w * 514 + 2 * x));
            int p = x >> 7, c = x & 127;
            if (c < 96) sm->gxpair[c][p] = s2;
        }
        __syncthreads();

        // ===== Gates for this rank's 32 h-indices x 4 batches ================
        if (tid < 128) {
            int p = gbb >> 1, comp = gbb & 1;
            int cc = 3 * gj;
            float gxr = pick(sm->gxpair[cc][p], comp);
            float gxz = pick(sm->gxpair[cc + 1][p], comp);
            float gxn = pick(sm->gxpair[cc + 2][p], comp);
            float ghr = pick(sm->ghpair[cc][p], comp);
            float ghz = pick(sm->ghpair[cc + 1][p], comp);
            float ghn = pick(sm->ghpair[cc + 2][p], comp);
            float r = 1.f / (1.f + __expf(-(gxr + bihr + ghr + bhhr)));
            float z = 1.f / (1.f + __expf(-(gxz + bihz + ghz + bhhz)));
            float n = tanhf(gxn + bihn + r * (ghn + bhhn));
            hreg = (1.f - z) * n + z * hreg;
            int i = 32 * rank + gj;
            out[(((size_t)(b_base + gbb)) * SLEN + s) * E + i] = hreg;
            sm->hstage[gbb][gj] = hreg;
        }
        __syncthreads();
        if (tid < 64) {  // pair-broadcast h to all 8 ranks
            int il = tid & 31, p = tid >> 5;
            int i = 32 * rank + il;
            u64 h2 = f2x2(sm->hstage[2 * p][il], sm->hstage[2 * p + 1][il]);
            uint32_t ah = s2u(&sm->hpair[i * 2 + p]);
#pragma unroll
            for (uint32_t rr = 0; rr < CLU; rr++) stc64(ah, rr, h2);
        }
        csync();  // #3: h(s+1) pairs ready
    }
}

extern "C" void kernel_launch(void* const* d_in, const int* in_sizes, int n_in,
                              void* d_out, int out_size) {
    const float* sig = (const float*)d_in[0];
    const float* bases = (const float*)d_in[1];
    const uint32_t* mask = (const uint32_t*)d_in[2];
    const float* Ww = (const float*)d_in[3];
    const float* Wb = (const float*)d_in[4];
    const float* lng = (const float*)d_in[5];
    const float* lnb = (const float*)d_in[6];
    const float* wih = (const float*)d_in[7];
    const float* bihp = (const float*)d_in[8];
    const float* whh = (const float*)d_in[9];
    const float* bhhp = (const float*)d_in[10];
    const float* h0 = (const float*)d_in[11];
    float* out = (float*)d_out;

    cudaFuncSetAttribute(gru, cudaFuncAttributeMaxDynamicSharedMemorySize,
                         (int)sizeof(SM));
    prep<<<3072, 256>>>(Ww, wih, whh);
    gru<<<256, NTHR, sizeof(SM)>>>(sig, bases, mask, Wb, lng, lnb, bihp, bhhp, h0, out);
}

// round 17
// speedup vs baseline: 1.1311x; 1.0177x over previous
#include <cuda_runtime.h>
#include <cstdint>

#define E 256
#define SLEN 64
#define TLEN 512
#define CLU 8
#define NTHR 256
#define BPC 4

typedef unsigned long long u64;

// WA:  [k=256][1024 cols]. Rank r owns cols [128r,128r+128):
//   c<32: W_w row (32r+c) (v, scattered to batch-owner pair)
//   c>=32: cc=c-32=3j+g: w_hh row (g*256+32r+j) (gh triplets, local)
// WX2: [k=512][768 cols] NO PAD. Rank r owns cols [96r,96r+96):
//   cc=3j+g -> w_ih row (g*256+32r+j)
__device__ float4 g_WA[256 * 256];
__device__ float4 g_WX[512 * 192];

__global__ void prep(const float* __restrict__ Ww, const float* __restrict__ wih,
                     const float* __restrict__ whh) {
    int idx = blockIdx.x * blockDim.x + threadIdx.x;
    float* WA = (float*)g_WA;
    float* WX = (float*)g_WX;
    if (idx < 256 * 1024) {
        int k = idx >> 10, cg = idx & 1023, r = cg >> 7, c = cg & 127;
        if (c < 32) WA[idx] = Ww[(32 * r + c) * 256 + k];
        else {
            int cc = c - 32, j = cc / 3, g = cc - 3 * j;
            WA[idx] = whh[(g * 256 + 32 * r + j) * 256 + k];
        }
    }
    int idx2 = idx - 256 * 1024;
    if (idx2 >= 0 && idx2 < 512 * 768) {
        int k = idx2 / 768, c = idx2 - k * 768;
        int r = c / 96, cc = c - 96 * r;
        int j = cc / 3, g = cc - 3 * j;
        WX[idx2] = wih[(g * 256 + 32 * r + j) * 512 + k];
    }
}

// ---------------- helpers ----------------------------------------------------
__device__ __forceinline__ u64 f2x2(float a, float b) {
    u64 r; asm("mov.b64 %0,{%1,%2};" : "=l"(r) : "f"(a), "f"(b)); return r;
}
__device__ __forceinline__ void unpk(u64 v, float& a, float& b) {
    asm("mov.b64 {%0,%1},%2;" : "=f"(a), "=f"(b) : "l"(v));
}
__device__ __forceinline__ u64 fma2(u64 a, u64 b, u64 c) {
    u64 d; asm("fma.rn.f32x2 %0,%1,%2,%3;" : "=l"(d) : "l"(a), "l"(b), "l"(c)); return d;
}
__device__ __forceinline__ u64 mul2(u64 a, u64 b) {
    u64 d; asm("mul.rn.f32x2 %0,%1,%2;" : "=l"(d) : "l"(a), "l"(b)); return d;
}
__device__ __forceinline__ u64 add2(u64 a, u64 b) {
    u64 d; asm("add.rn.f32x2 %0,%1,%2;" : "=l"(d) : "l"(a), "l"(b)); return d;
}
__device__ __forceinline__ uint32_t s2u(const void* p) {
    return (uint32_t)__cvta_generic_to_shared(p);
}
__device__ __forceinline__ void stc64(uint32_t a, uint32_t rk, u64 v) {
    uint32_t ra;
    asm volatile("mapa.shared::cluster.u32 %0,%1,%2;" : "=r"(ra) : "r"(a), "r"(rk));
    asm volatile("st.shared::cluster.u64 [%0],%1;" ::"r"(ra), "l"(v) : "memory");
}
__device__ __forceinline__ void stc32(uint32_t a, uint32_t rk, float v) {
    uint32_t ra;
    asm volatile("mapa.shared::cluster.u32 %0,%1,%2;" : "=r"(ra) : "r"(a), "r"(rk));
    asm volatile("st.shared::cluster.f32 [%0],%1;" ::"r"(ra), "f"(v) : "memory");
}
__device__ __forceinline__ void csync() {
    asm volatile("barrier.cluster.arrive.aligned;" ::: "memory");
    asm volatile("barrier.cluster.wait.aligned;" ::: "memory");
}
__device__ __forceinline__ float pick(u64 v, int comp) {
    float lo, hi; unpk(v, lo, hi);
    return comp ? hi : lo;
}

struct __align__(16) SM {
    u64 hpair[256 * 2];      // (h_{2p}, h_{2p+1}) per [k][p]
    u64 lnpair[512 * 2];     // (y_{2p}, y_{2p+1}) per [k][p] — local only
    float part[8 * 514];     // matvec partials / ctx scratch
    float ctxh[8][260];      // raw ctx halves from all 8 ranks
    float2 mSall[8];         // (m,S) from all 8 ranks
    float v_own[E];
    u64 ghpair[96][2];       // gh pairs [cc][p]
    u64 gxpair[96][2];       // gx pairs [cc][p]
    float hstage[4][33];     // gate outputs staging for pair-broadcast
    float lngS[512];
    float lnbS[512];
    float muS[4];
    float rsS[4];
    float2 mS[8];
    float wgtS[8];
    float redA[12];
    float redB[12];
};

// Batch-pair packed matvec (phase A): 4 cols/lane x 2 pairs; warp = KW k's.
template <int KW>
__device__ __forceinline__ void matpair(const float4* __restrict__ W4,
                                        const u64* __restrict__ hp_,
                                        float* part, int lane, int warp, int rank) {
    u64 acc[4][2];
#pragma unroll
    for (int c = 0; c < 4; c++) { acc[c][0] = 0ull; acc[c][1] = 0ull; }
    const float4* wp = W4 + (size_t)(warp * KW) * 256 + rank * 32 + lane;
    const u64* hp = hp_ + (warp * KW) * 2;
#pragma unroll 4
    for (int k = 0; k < KW; k++) {
        float4 w = wp[0]; wp += 256;
        u64 h0 = hp[0], h1 = hp[1]; hp += 2;
        u64 w0 = f2x2(w.x, w.x), w1 = f2x2(w.y, w.y);
        u64 w2 = f2x2(w.z, w.z), w3 = f2x2(w.w, w.w);
        acc[0][0] = fma2(w0, h0, acc[0][0]); acc[0][1] = fma2(w0, h1, acc[0][1]);
        acc[1][0] = fma2(w1, h0, acc[1][0]); acc[1][1] = fma2(w1, h1, acc[1][1]);
        acc[2][0] = fma2(w2, h0, acc[2][0]); acc[2][1] = fma2(w2, h1, acc[2][1]);
        acc[3][0] = fma2(w3, h0, acc[3][0]); acc[3][1] = fma2(w3, h1, acc[3][1]);
    }
#pragma unroll
    for (int c = 0; c < 4; c++)
#pragma unroll
        for (int p = 0; p < 2; p++)
            *(u64*)(part + warp * 514 + 2 * (p * 128 + 4 * lane + c)) = acc[c][p];
}

// gx matvec, no padding: 24 active lanes x 4 cols; warp = 64 k's.
__device__ __forceinline__ void matpairX(const float4* __restrict__ W4,
                                         const u64* __restrict__ hp_,
                                         float* part, int lane, int warp, int rank) {
    int ll = lane < 24 ? lane : 23;
    u64 acc[4][2];
#pragma unroll
    for (int c = 0; c < 4; c++) { acc[c][0] = 0ull; acc[c][1] = 0ull; }
    const float4* wp = W4 + (size_t)(warp * 64) * 192 + rank * 24 + ll;
    const u64* hp = hp_ + (warp * 64) * 2;
#pragma unroll 4
    for (int k = 0; k < 64; k++) {
        float4 w = wp[0]; wp += 192;
        u64 h0 = hp[0], h1 = hp[1]; hp += 2;
        u64 w0 = f2x2(w.x, w.x), w1 = f2x2(w.y, w.y);
        u64 w2 = f2x2(w.z, w.z), w3 = f2x2(w.w, w.w);
        acc[0][0] = fma2(w0, h0, acc[0][0]); acc[0][1] = fma2(w0, h1, acc[0][1]);
        acc[1][0] = fma2(w1, h0, acc[1][0]); acc[1][1] = fma2(w1, h1, acc[1][1]);
        acc[2][0] = fma2(w2, h0, acc[2][0]); acc[2][1] = fma2(w2, h1, acc[2][1]);
        acc[3][0] = fma2(w3, h0, acc[3][0]); acc[3][1] = fma2(w3, h1, acc[3][1]);
    }
    if (lane < 24) {
#pragma unroll
        for (int c = 0; c < 4; c++)
#pragma unroll
            for (int p = 0; p < 2; p++)
                *(u64*)(part + warp * 386 + 2 * (p * 96 + 4 * lane + c)) = acc[c][p];
    }
}

__global__ void __cluster_dims__(CLU, 1, 1) __launch_bounds__(NTHR, 2)
gru(const float* __restrict__ sig, const float* __restrict__ bases,
    const uint32_t* __restrict__ mask, const float* __restrict__ Wb,
    const float* __restrict__ lng, const float* __restrict__ lnb,
    const float* __restrict__ bih, const float* __restrict__ bhh,
    const float* __restrict__ h0, float* __restrict__ out) {
    extern __shared__ char smraw[];
    SM* sm = (SM*)smraw;
    const int tid = threadIdx.x, lane = tid & 31, warp = tid >> 5;
    uint32_t rank;
    asm("mov.u32 %0,%%cluster_ctarank;" : "=r"(rank));
    const int b_base = (blockIdx.x >> 3) * BPC;
    const int b = b_base + (int)(rank >> 1);
    const int toff = (rank & 1) * 256;
    const float NEGINF = __int_as_float(0xff800000);

    float bihr = 0.f, bihz = 0.f, bihn = 0.f;
    float bhhr = 0.f, bhhz = 0.f, bhhn = 0.f, hreg = 0.f;
    const int gj = tid & 31, gbb = tid >> 5;
    if (tid < 128) {
        int i = 32 * rank + gj;
        bihr = bih[i]; bihz = bih[256 + i]; bihn = bih[512 + i];
        bhhr = bhh[i]; bhhz = bhh[256 + i]; bhhn = bhh[512 + i];
        hreg = h0[i];
    }
    {
        float hv = h0[tid];
        u64 h2 = f2x2(hv, hv);
        sm->hpair[tid * 2 + 0] = h2;
        sm->hpair[tid * 2 + 1] = h2;
        sm->lngS[tid] = lng[tid];       sm->lngS[256 + tid] = lng[256 + tid];
        sm->lnbS[tid] = lnb[tid];       sm->lnbS[256 + tid] = lnb[256 + tid];
    }
    const ulonglong2 wbA = ((const ulonglong2*)Wb)[2 * lane];
    const ulonglong2 wbB = ((const ulonglong2*)Wb)[2 * lane + 1];
    // step-invariant mask as per-warp ballot: bit j = row (warp*32+j) masked
    uint32_t mskbits;
    {
        uint32_t mv = mask[(size_t)b * TLEN + toff + warp * 32 + lane];
        mskbits = __ballot_sync(0xffffffffu, mv != 0u);
    }
    __syncthreads();
    csync();

    const ulonglong2* sq = (const ulonglong2*)(sig + (size_t)b * TLEN * E);

    for (int s = 0; s < SLEN; s++) {
        // ===== Phase A: v (to batch-owner pair) + gh (local), packed ========
        matpair<32>(g_WA, sm->hpair, sm->part, lane, warp, rank);
        __syncthreads();
        {
            int x = tid;  // u64 slot: p = x>>7, col c = x&127
            u64 s2 = 0ull;
#pragma unroll
            for (int w = 0; w < 8; w++)
                s2 = add2(s2, *(const u64*)(sm->part + w * 514 + 2 * x));
            int p = x >> 7, c = x & 127;
            if (c < 32) {
                float lo, hi; unpk(s2, lo, hi);
                uint32_t a = s2u(&sm->v_own[32 * rank + c]);
                stc32(a, (uint32_t)(4 * p + 0), lo);
                stc32(a, (uint32_t)(4 * p + 1), lo);
                stc32(a, (uint32_t)(4 * p + 2), hi);
                stc32(a, (uint32_t)(4 * p + 3), hi);
            } else sm->ghpair[c - 32][p] = s2;
        }
        csync();  // #1: v ready

        // ===== Attention: own batch, own 256-row T-half, 32 rows/warp =======
        ulonglong2 vr0 = ((const ulonglong2*)sm->v_own)[2 * lane];
        ulonglong2 vr1 = ((const ulonglong2*)sm->v_own)[2 * lane + 1];
        ulonglong2 va, vb;
        va.x = add2(vr0.x, wbA.x); va.y = add2(vr0.y, wbA.y);
        vb.x = add2(vr1.x, wbB.x); vb.y = add2(vr1.y, wbB.y);
        float mrun = -1e30f, Ss = 0.f;
        u64 c0 = 0, c1 = 0, c2 = 0, c3 = 0;
#pragma unroll 2
        for (int g = 0; g < 8; g++) {
            int tl = warp * 32 + g * 4;
            size_t tg = (size_t)(toff + tl) * 64;
            ulonglong2 r0a = sq[tg + 2 * lane],       r0b = sq[tg + 2 * lane + 1];
            ulonglong2 r1a = sq[tg + 64 + 2 * lane],  r1b = sq[tg + 64 + 2 * lane + 1];
            ulonglong2 r2a = sq[tg + 128 + 2 * lane], r2b = sq[tg + 128 + 2 * lane + 1];
            ulonglong2 r3a = sq[tg + 192 + 2 * lane], r3b = sq[tg + 192 + 2 * lane + 1];
            auto dotp = [&](ulonglong2 ra, ulonglong2 rb) {
                u64 a = mul2(ra.x, va.x);
                a = fma2(ra.y, va.y, a);
                a = fma2(rb.x, vb.x, a);
                a = fma2(rb.y, vb.y, a);
                float lo, hi; unpk(a, lo, hi);
                return lo + hi;
            };
            float a0 = dotp(r0a, r0b), a1 = dotp(r1a, r1b);
            float a2 = dotp(r2a, r2b), a3 = dotp(r3a, r3b);
#pragma unroll
            for (int o = 16; o; o >>= 1) {
                a0 += __shfl_xor_sync(0xffffffffu, a0, o);
                a1 += __shfl_xor_sync(0xffffffffu, a1, o);
                a2 += __shfl_xor_sync(0xffffffffu, a2, o);
                a3 += __shfl_xor_sync(0xffffffffu, a3, o);
            }
            uint32_t mb = (mskbits >> (g * 4)) & 0xFu;
            if (mb & 1u) a0 = NEGINF;
            if (mb & 2u) a1 = NEGINF;
            if (mb & 4u) a2 = NEGINF;
            if (mb & 8u) a3 = NEGINF;
            float mg = fmaxf(fmaxf(a0, a1), fmaxf(a2, a3));
            if (mg > mrun) {
                float sc = __expf(mrun - mg);
                mrun = mg; Ss *= sc;
                u64 sc2 = f2x2(sc, sc);
                c0 = mul2(c0, sc2); c1 = mul2(c1, sc2);
                c2 = mul2(c2, sc2); c3 = mul2(c3, sc2);
            }
            float p0 = __expf(a0 - mrun), p1 = __expf(a1 - mrun);
            float p2 = __expf(a2 - mrun), p3 = __expf(a3 - mrun);
            Ss += (p0 + p1) + (p2 + p3);
            u64 q0 = f2x2(p0, p0), q1 = f2x2(p1, p1), q2 = f2x2(p2, p2), q3 = f2x2(p3, p3);
            c0 = fma2(q0, r0a.x, c0); c1 = fma2(q0, r0a.y, c1);
            c2 = fma2(q0, r0b.x, c2); c3 = fma2(q0, r0b.y, c3);
            c0 = fma2(q1, r1a.x, c0); c1 = fma2(q1, r1a.y, c1);
            c2 = fma2(q1, r1b.x, c2); c3 = fma2(q1, r1b.y, c3);
            c0 = fma2(q2, r2a.x, c0); c1 = fma2(q2, r2a.y, c1);
            c2 = fma2(q2, r2b.x, c2); c3 = fma2(q2, r2b.y, c3);
            c0 = fma2(q3, r3a.x, c0); c1 = fma2(q3, r3a.y, c1);
            c2 = fma2(q3, r3b.x, c2); c3 = fma2(q3, r3b.y, c3);
        }
        {
            u64* cw = (u64*)sm->part + warp * 132 + lane * 4;
            cw[0] = c0; cw[1] = c1; cw[2] = c2; cw[3] = c3;
            if (lane == 0) sm->mS[warp] = make_float2(mrun, Ss);
        }
        __syncthreads();
        if (tid < 32) {
            float mw = (lane < 8) ? sm->mS[lane].x : NEGINF;
            float Sw = (lane < 8) ? sm->mS[lane].y : 0.f;
            float m = mw;
#pragma unroll
            for (int o = 16; o; o >>= 1) m = fmaxf(m, __shfl_xor_sync(0xffffffffu, m, o));
            float wgt = __expf(mw - m);
            float Sc = Sw * wgt;
#pragma unroll
            for (int o = 16; o; o >>= 1) Sc += __shfl_xor_sync(0xffffffffu, Sc, o);
            if (lane < 8) sm->wgtS[lane] = wgt;
            if (lane == 0) {
                u64 msv = f2x2(m, Sc);
                uint32_t am = s2u(&sm->mSall[rank]);
#pragma unroll
                for (uint32_t rr = 0; rr < CLU; rr++) stc64(am, rr, msv);
            }
        }
        __syncthreads();
        {   // combine warp ctx partials; broadcast raw half to all 8 ranks
            float acc = 0.f;
#pragma unroll
            for (int w = 0; w < 8; w++) acc += sm->part[w * 264 + tid] * sm->wgtS[w];
            uint32_t ad = s2u(&sm->ctxh[rank][tid]);
#pragma unroll
            for (uint32_t rr = 0; rr < CLU; rr++) stc32(ad, rr, acc);
        }
        csync();  // #2: all ctx halves + (m,S) present everywhere

        // ===== Redundant merge + LN for all 4 batches (local) ===============
        {
            int bb = tid >> 6, e4 = (tid & 63) * 4;
            float2 m0 = sm->mSall[2 * bb], m1 = sm->mSall[2 * bb + 1];
            float m = fmaxf(m0.x, m1.x);
            float w0 = __expf(m0.x - m), w1 = __expf(m1.x - m);
            float invS = 1.f / (m0.y * w0 + m1.y * w1);
            float4 cA = *(float4*)&sm->ctxh[2 * bb][e4];
            float4 cB = *(float4*)&sm->ctxh[2 * bb + 1][e4];
            float4 cm;
            cm.x = (cA.x * w0 + cB.x * w1) * invS;
            cm.y = (cA.y * w0 + cB.y * w1) * invS;
            cm.z = (cA.z * w0 + cB.z * w1) * invS;
            cm.w = (cA.w * w0 + cB.w * w1) * invS;
            *(float4*)&sm->ctxh[2 * bb][e4] = cm;
        }
        __syncthreads();
        {
            int bb = warp >> 1, half = warp & 1;
            float s1, s2;
            if (half == 0) {
                const float4* xb = (const float4*)(bases +
                    ((size_t)(b_base + bb) * SLEN + s) * E);
                float4 xa = xb[2 * lane], xc = xb[2 * lane + 1];
                s1 = (xa.x + xa.y + xa.z + xa.w) + (xc.x + xc.y + xc.z + xc.w);
                s2 = xa.x * xa.x + xa.y * xa.y + xa.z * xa.z + xa.w * xa.w +
                     xc.x * xc.x + xc.y * xc.y + xc.z * xc.z + xc.w * xc.w;
            } else {
                const float4* cb = (const float4*)&sm->ctxh[2 * bb][0];
                float4 xa = cb[2 * lane], xc = cb[2 * lane + 1];
                s1 = (xa.x + xa.y + xa.z + xa.w) + (xc.x + xc.y + xc.z + xc.w);
                s2 = xa.x * xa.x + xa.y * xa.y + xa.z * xa.z + xa.w * xa.w +
                     xc.x * xc.x + xc.y * xc.y + xc.z * xc.z + xc.w * xc.w;
            }
#pragma unroll
            for (int o = 16; o; o >>= 1) {
                s1 += __shfl_xor_sync(0xffffffffu, s1, o);
                s2 += __shfl_xor_sync(0xffffffffu, s2, o);
            }
            if (lane == 0) { sm->redA[warp] = s1; sm->redB[warp] = s2; }
            __syncthreads();
            if (tid < 4) {
                float t1 = sm->redA[2 * tid] + sm->redA[2 * tid + 1];
                float t2 = sm->redB[2 * tid] + sm->redB[2 * tid + 1];
                float mu = t1 * (1.f / 512.f);
                float var = t2 * (1.f / 512.f) - mu * mu;
                sm->muS[tid] = mu;
                sm->rsS[tid] = rsqrtf(var + 1e-5f);
            }
            __syncthreads();
        }
        {   // y-write, batch-pair packed, STS.128
            float g0 = sm->lngS[tid], b0v = sm->lnbS[tid];
            float g1 = sm->lngS[256 + tid], b1v = sm->lnbS[256 + tid];
            ulonglong2 y0p, y1p;
#pragma unroll
            for (int p = 0; p < 2; p++) {
                float mu0 = sm->muS[2 * p], rs0 = sm->rsS[2 * p];
                float mu1 = sm->muS[2 * p + 1], rs1 = sm->rsS[2 * p + 1];
                float xv0 = bases[((size_t)(b_base + 2 * p) * SLEN + s) * E + tid];
                float xv1 = bases[((size_t)(b_base + 2 * p + 1) * SLEN + s) * E + tid];
                float cv0 = sm->ctxh[4 * p][tid];
                float cv1 = sm->ctxh[4 * p + 2][tid];
                u64 ya = f2x2((xv0 - mu0) * rs0 * g0 + b0v, (xv1 - mu1) * rs1 * g0 + b0v);
                u64 yb = f2x2((cv0 - mu0) * rs0 * g1 + b1v, (cv1 - mu1) * rs1 * g1 + b1v);
                if (p == 0) { y0p.x = ya; y1p.x = yb; }
                else        { y0p.y = ya; y1p.y = yb; }
            }
            *(ulonglong2*)&sm->lnpair[tid * 2] = y0p;
            *(ulonglong2*)&sm->lnpair[(256 + tid) * 2] = y1p;
        }
        __syncthreads();

        // ===== Phase C: gx (local triplets), packed, no pad ==================
        matpairX(g_WX, sm->lnpair, sm->part, lane, warp, rank);
        __syncthreads();
        if (tid < 192) {
            int p = (tid >= 96) ? 1 : 0, c = tid - 96 * p;
            u64 s2 = 0ull;
#pragma unroll
            for (int w = 0; w < 8; w++)
                s2 = add2(s2, *(const u64*)(sm->part + w * 386 + 2 * tid));
            sm->gxpair[c][p] = s2;
        }
        __syncthreads();

        // ===== Gates for this rank's 32 h-indices x 4 batches ================
        if (tid < 128) {
            int p = gbb >> 1, comp = gbb & 1;
            int cc = 3 * gj;
            float gxr = pick(sm->gxpair[cc][p], comp);
            float gxz = pick(sm->gxpair[cc + 1][p], comp);
            float gxn = pick(sm->gxpair[cc + 2][p], comp);
            float ghr = pick(sm->ghpair[cc][p], comp);
            float ghz = pick(sm->ghpair[cc + 1][p], comp);
            float ghn = pick(sm->ghpair[cc + 2][p], comp);
            float r = 1.f / (1.f + __expf(-(gxr + bihr + ghr + bhhr)));
            float z = 1.f / (1.f + __expf(-(gxz + bihz + ghz + bhhz)));
            float n = tanhf(gxn + bihn + r * (ghn + bhhn));
            hreg = (1.f - z) * n + z * hreg;
            int i = 32 * rank + gj;
            out[(((size_t)(b_base + gbb)) * SLEN + s) * E + i] = hreg;
            sm->hstage[gbb][gj] = hreg;
        }
        __syncthreads();
        if (tid < 64) {  // pair-broadcast h to all 8 ranks
            int il = tid & 31, p = tid >> 5;
            int i = 32 * rank + il;
            u64 h2 = f2x2(sm->hstage[2 * p][il], sm->hstage[2 * p + 1][il]);
            uint32_t ah = s2u(&sm->hpair[i * 2 + p]);
#pragma unroll
            for (uint32_t rr = 0; rr < CLU; rr++) stc64(ah, rr, h2);
        }
        csync();  // #3: h(s+1) pairs ready
    }
}

extern "C" void kernel_launch(void* const* d_in, const int* in_sizes, int n_in,
                              void* d_out, int out_size) {
    const float* sig = (const float*)d_in[0];
    const float* bases = (const float*)d_in[1];
    const uint32_t* mask = (const uint32_t*)d_in[2];
    const float* Ww = (const float*)d_in[3];
    const float* Wb = (const float*)d_in[4];
    const float* lng = (const float*)d_in[5];
    const float* lnb = (const float*)d_in[6];
    const float* wih = (const float*)d_in[7];
    const float* bihp = (const float*)d_in[8];
    const float* whh = (const float*)d_in[9];
    const float* bhhp = (const float*)d_in[10];
    const float* h0 = (const float*)d_in[11];
    float* out = (float*)d_out;

    cudaFuncSetAttribute(gru, cudaFuncAttributeMaxDynamicSharedMemorySize,
                         (int)sizeof(SM));
    prep<<<2624, 256>>>(Ww, wih, whh);
    gru<<<256, NTHR, sizeof(SM)>>>(sig, bases, mask, Wb, lng, lnb, bihp, bhhp, h0, out);
}